// round 8
// baseline (speedup 1.0000x reference)
#include <cuda_runtime.h>

// QuantumRegression: 1024 x 14-qubit statevector sim, 3 layers (Rot per wire + CNOT ring),
// <Z_w> features, linear head.
//
// R8: ZYZ factorization. Each Rot gate U = e^{ia} RZ(beta) RY(gamma) RZ(delta); within a
// pass (distinct bits) all RZ factors commute out: pass = [diag] [real RYs] [diag], with
// the diagonals precomputed as 32-entry phase tables. FMA2 per layer drops 1792 -> 1280.
// Global phases and the final pass's exit diagonal are dropped (|amp|^2 phase-invariant).
// Frame-tracked CNOT perms, XOR-staggered pass C, Walsh measurement as in R7. NT=512.

#define NW   14
#define DIM  16384
#define NT   512

typedef unsigned long long u64;

__device__ float4 g_diag[576];     // [pass(9)][half(2: 0=entry,1=exit)][f(32)] : {pr,pr,-pi,pi}
__device__ float2 g_rot[3*NW];     // per-wire (cos g/2, sin g/2)

// ---------------- setup: ZYZ decomposition + diagonal tables ----------------

struct cpx { float re, im; };
__device__ __forceinline__ cpx cmul(cpx a, cpx b){
    cpx r; r.re = a.re*b.re - a.im*b.im; r.im = a.re*b.im + a.im*b.re; return r;
}

__device__ void rotmat(const float* p, cpx U[2][2]){
    float cx = cosf(0.5f*p[0]), sx = sinf(0.5f*p[0]);
    float cy = cosf(0.5f*p[1]), sy = sinf(0.5f*p[1]);
    float cz = cosf(0.5f*p[2]), sz = sinf(0.5f*p[2]);
    cpx r00 = { cy*cx,  sy*sx};
    cpx r01 = {-sy*cx, -cy*sx};
    cpx r10 = { sy*cx, -cy*sx};
    cpx r11 = { cy*cx, -sy*sx};
    cpx e0 = {cz, -sz}, e1 = {cz, sz};
    U[0][0] = cmul(e0, r00); U[0][1] = cmul(e0, r01);
    U[1][0] = cmul(e1, r10); U[1][1] = cmul(e1, r11);
}

__global__ void setup_all(const float* __restrict__ vp){
    __shared__ float sbeta[3*NW], sdelta[3*NW];
    int t = threadIdx.x;
    if (t < 3*NW){
        cpx U[2][2]; rotmat(vp + t*3, U);
        float na = hypotf(U[0][0].re, U[0][0].im);
        float nc = hypotf(U[1][0].re, U[1][0].im);
        float n  = hypotf(na, nc);
        g_rot[t] = make_float2(na/n, nc/n);     // (cos g/2, sin g/2), both >= 0
        float beta, delta;
        if (nc > 1e-6f && na > 1e-6f){
            float aa = atan2f(U[0][0].im, U[0][0].re);
            float ac = atan2f(U[1][0].im, U[1][0].re);
            float ad = atan2f(U[1][1].im, U[1][1].re);
            beta = ac - aa; delta = ad - ac;
        } else if (nc <= 1e-6f){                // gamma ~ 0: U = e^{ia} RZ(beta)
            delta = 0.f;
            beta = atan2f(U[1][1].im, U[1][1].re) - atan2f(U[0][0].im, U[0][0].re);
        } else {                                // gamma ~ pi
            delta = 0.f;
            beta = atan2f(U[1][0].im, U[1][0].re) - atan2f(-U[0][1].im, -U[0][1].re);
        }
        sbeta[t] = beta; sdelta[t] = delta;
    }
    __syncthreads();
    if (t < 576){
        int p = t >> 6, h = (t >> 5) & 1, f = t & 31;
        int l = p / 3, typ = p % 3;
        int nb = (typ == 2) ? 4 : 5;
        int w0 = l*NW + (typ == 0 ? 4 : (typ == 1 ? 9 : 13));  // wire for f-bit 0 ... w0-k for bit k
        const float* src = h ? sbeta : sdelta;
        float ang = 0.f;
        for (int k = 0; k < nb; k++){
            float half = 0.5f * src[w0 - k];
            ang += ((f >> k) & 1) ? half : -half;   // RZ: bit0 -> e^{-i*/2}, bit1 -> e^{+i*/2}
        }
        float sp, cp; sincosf(ang, &sp, &cp);
        g_diag[t] = make_float4(cp, cp, -sp, sp);
    }
}

// ---------------- packed f32x2 helpers ----------------

__device__ __forceinline__ u64 pk2(float lo, float hi){
    u64 r; asm("mov.b64 %0, {%1,%2};" : "=l"(r) : "f"(lo), "f"(hi)); return r;
}
__device__ __forceinline__ void upk2(u64 v, float& lo, float& hi){
    asm("mov.b64 {%0,%1}, %2;" : "=f"(lo), "=f"(hi) : "l"(v));
}
__device__ __forceinline__ u64 swp2(u64 v){
    u64 r;
    asm("{ .reg .b32 a,b; mov.b64 {a,b}, %1; mov.b64 %0, {b,a}; }" : "=l"(r) : "l"(v));
    return r;
}
__device__ __forceinline__ u64 f2(u64 a, u64 b, u64 c){
    u64 r; asm("fma.rn.f32x2 %0, %1, %2, %3;" : "=l"(r) : "l"(a), "l"(b), "l"(c)); return r;
}
__device__ __forceinline__ u64 m2(u64 a, u64 b){
    u64 r; asm("mul.rn.f32x2 %0, %1, %2;" : "=l"(r) : "l"(a), "l"(b)); return r;
}

// diagonal: amp[m] *= tab[m ^ u]  (complex phase)
template<int N>
__device__ __forceinline__ void diagN(u64* amp, const float4* tab, int u){
    #pragma unroll
    for (int m = 0; m < N; m++){
        float4 q = tab[m ^ u];
        u64 uu = pk2(q.x, q.y), nn = pk2(q.z, q.w);
        amp[m] = f2(uu, amp[m], m2(nn, swp2(amp[m])));
    }
}

// NB real RY rotations on bits NB-1..0 of a 2^NB-amp tile; bit k <-> wire w0-k.
// u-bit set => logical 0/1 roles swapped => s -> -s.
template<int NB>
__device__ __forceinline__ void rotTile(u64* amp, const float2* rot, int w0, int u){
    #pragma unroll
    for (int k = NB-1; k >= 0; k--){
        float2 cs = rot[w0 - k];
        float s = ((u >> k) & 1) ? -cs.y : cs.y;
        u64 cc = pk2(cs.x, cs.x), ss = pk2(s, s), ns = pk2(-s, -s);
        const int bit = 1 << k;
        #pragma unroll
        for (int p = 0; p < (1 << NB); p++)
            if (!(p & bit)){
                u64 v0 = amp[p], v1 = amp[p | bit];
                amp[p]       = f2(cc, v0, m2(ns, v1));
                amp[p | bit] = f2(cc, v1, m2(ss, v0));
            }
    }
}

// ---------------- CNOT-ring permutation (GF2 linear, constexpr-foldable) ----------------
__host__ __device__ __forceinline__ constexpr int cpfwd(int i){
    int y = i;
    y ^= y >> 1; y ^= y >> 2; y ^= y >> 4; y ^= y >> 8;
    return (y & 0x1FFF) ^ ((((y ^ (i >> 13)) & 1) << 13));
}
__host__ __device__ __forceinline__ constexpr int cpinv(int o){
    int t = o ^ (o >> 1);
    return (t & 0x1FFF) ^ (o & 0x2000) ^ ((o & 1) ? 0x3000 : 0);
}
template<int L>
__host__ __device__ __forceinline__ constexpr int pinvL(int x){
    return (L == 0) ? x : (L == 1) ? cpinv(x) : cpinv(cpinv(x));
}

// ---------------- passes ----------------

// 5-wire 32-amp pass at logical bits S+4..S, layer L. One tile per thread (NT=512).
template<int L, int S>
__device__ __forceinline__ void passG32(float2* psi, const float4* sdiag, const float2* srot, int t){
    const float4* tab = sdiag + (L*3 + (S == 9 ? 0 : 1)) * 64;
    const int w0 = L*NW + (S == 9 ? 4 : 9);
    int x = ((t >> S) << (S+5)) | (t & ((1 << S) - 1));
    int base = pinvL<L>(x);
    u64 amp[32];
    #pragma unroll
    for (int f = 0; f < 32; f++){
        float2 a = psi[base ^ pinvL<L>(f << S)];
        amp[f] = pk2(a.x, a.y);
    }
    diagN<32>(amp, tab, 0);
    rotTile<5>(amp, srot, w0, 0);
    diagN<32>(amp, tab + 32, 0);
    #pragma unroll
    for (int f = 0; f < 32; f++){
        float xx, yy; upk2(amp[f], xx, yy);
        psi[base ^ pinvL<L>(f << S)] = make_float2(xx, yy);
    }
}

// stagger offset u for C passes: u = A_L^{-1}((lane&15) ^ base_low4)
template<int L>
__device__ __forceinline__ int p3stagger(int t){
    int r4 = t & 15;
    if (L == 0) return r4;
    if (L == 1){ int v = r4 ^ ((t & 1) << 3); return (v ^ (v>>1) ^ (v>>2) ^ (v>>3)) & 15; }
    int v = r4 ^ ((t & 3) << 2); return (v ^ (v >> 2)) & 15;
}

// 4-wire pass at logical bits 3..0 (wires 10..13), layer L; MEAS folds P^3 measurement
// (exit diagonal skipped when MEAS: |amp|^2 is phase-invariant).
template<int L, bool MEAS>
__device__ __forceinline__ void passC(float2* psi, const float4* sdiag, const float2* srot,
                                      int t, float* zs){
    const float4* tab = sdiag + (L*3 + 2) * 64;
    const int u = p3stagger<L>(t);
    const int uoff = pinvL<L>(u);
    #pragma unroll 1
    for (int tt = 0; tt < DIM/16/NT; tt++){
        int y = t + NT*tt;                        // 10-bit tile index
        int base = pinvL<L>(y << 4) ^ uoff;
        u64 amp[16];
        #pragma unroll
        for (int m = 0; m < 16; m++){
            float2 a = psi[base ^ pinvL<L>(m)];
            amp[m] = pk2(a.x, a.y);
        }
        diagN<16>(amp, tab, u);
        rotTile<4>(amp, srot, L*NW + 13, u);
        if (!MEAS){
            diagN<16>(amp, tab + 32, u);
            #pragma unroll
            for (int m = 0; m < 16; m++){
                float xx, yy; upk2(amp[m], xx, yy);
                psi[base ^ pinvL<L>(m)] = make_float2(xx, yy);
            }
        } else {
            // logical o = cpfwd((y<<4) ^ u ^ m); cpfwd(m) sign bits live in o bits 3..0,13
            int obase = cpfwd((y << 4) ^ u);
            float pr[16];
            #pragma unroll
            for (int m = 0; m < 16; m++){
                float xx, yy; upk2(amp[m], xx, yy);
                pr[m] = xx*xx + yy*yy;
            }
            // partial Walsh butterfly over m bits b0..b3:
            //   o bit0 = b0^b1^b2^b3 (also bit13), bit1 = b1^b2^b3, bit2 = b2^b3, bit3 = b3
            float P[8], Mv[8];
            #pragma unroll
            for (int j = 0; j < 8; j++){ P[j] = pr[2*j] + pr[2*j+1]; Mv[j] = pr[2*j] - pr[2*j+1]; }
            float Spar = Mv[0]-Mv[1]-Mv[2]+Mv[3]-Mv[4]+Mv[5]+Mv[6]-Mv[7];
            float PP[4], PM[4];
            #pragma unroll
            for (int k = 0; k < 4; k++){ PP[k] = P[2*k] + P[2*k+1]; PM[k] = P[2*k] - P[2*k+1]; }
            float S123 = PM[0]-PM[1]-PM[2]+PM[3];
            float PPP0 = PP[0]+PP[1], PPP1 = PP[2]+PP[3];
            float S23  = (PP[0]-PP[1]) - (PP[2]-PP[3]);
            float T    = PPP0 + PPP1;
            float S3   = PPP0 - PPP1;
            #pragma unroll
            for (int w = 1; w <= 9; w++){
                unsigned msk = ((unsigned)obase << (18 + w)) & 0x80000000u;
                zs[w] += __uint_as_float(__float_as_uint(T) ^ msk);
            }
            zs[0]  += __uint_as_float(__float_as_uint(Spar) ^ (((unsigned)obase << 18) & 0x80000000u)); // bit13
            zs[13] += __uint_as_float(__float_as_uint(Spar) ^ (((unsigned)obase << 31) & 0x80000000u)); // bit0
            zs[12] += __uint_as_float(__float_as_uint(S123) ^ (((unsigned)obase << 30) & 0x80000000u)); // bit1
            zs[11] += __uint_as_float(__float_as_uint(S23)  ^ (((unsigned)obase << 29) & 0x80000000u)); // bit2
            zs[10] += __uint_as_float(__float_as_uint(S3)   ^ (((unsigned)obase << 28) & 0x80000000u)); // bit3
        }
    }
}

// ---------------- main kernel ----------------

__global__ void __launch_bounds__(NT, 1)
qsim_kernel(const float* __restrict__ sr, const float* __restrict__ si,
            const float* __restrict__ hw, const float* __restrict__ hb,
            float* __restrict__ out)
{
    extern __shared__ float2 sm[];
    float2* psi = sm;
    float4* sdiag = reinterpret_cast<float4*>(sm + DIM);              // 576 float4
    float2* srot  = reinterpret_cast<float2*>(sdiag + 576);           // 42 float2
    const int t = threadIdx.x;
    const int b = blockIdx.x;

    // stage tables into smem
    #pragma unroll
    for (int i = t; i < 576; i += NT) sdiag[i] = g_diag[i];
    if (t < 3*NW) srot[t] = g_rot[t];
    __syncthreads();

    // ---- layer 0 pass A (wires 0..4, bits 13..9) fused with global load ----
    {
        const float* srb = sr + (size_t)b * DIM;
        const float* sib = si + (size_t)b * DIM;
        u64 amp[32];
        #pragma unroll
        for (int f = 0; f < 32; f++){
            float re = __ldg(srb + (f << 9) + t);
            float im = __ldg(sib + (f << 9) + t);
            amp[f] = pk2(re, im);
        }
        diagN<32>(amp, sdiag, 0);
        rotTile<5>(amp, srot, 4, 0);
        diagN<32>(amp, sdiag + 32, 0);
        #pragma unroll
        for (int f = 0; f < 32; f++){
            float x, y; upk2(amp[f], x, y);
            psi[(f << 9) + t] = make_float2(x, y);
        }
    }
    __syncthreads();
    passG32<0,4>(psi, sdiag, srot, t);       __syncthreads();
    passC<0,false>(psi, sdiag, srot, t, 0);  __syncthreads();

    passG32<1,9>(psi, sdiag, srot, t);       __syncthreads();
    passG32<1,4>(psi, sdiag, srot, t);       __syncthreads();
    passC<1,false>(psi, sdiag, srot, t, 0);  __syncthreads();

    passG32<2,9>(psi, sdiag, srot, t);       __syncthreads();
    passG32<2,4>(psi, sdiag, srot, t);       __syncthreads();

    // ---- layer 2 pass C + measurement (P^3 folded; exit diag dropped) ----
    float zs[NW];
    #pragma unroll
    for (int w = 0; w < NW; w++) zs[w] = 0.f;
    passC<2,true>(psi, sdiag, srot, t, zs);

    // warp reduce
    #pragma unroll
    for (int off = 16; off > 0; off >>= 1)
        #pragma unroll
        for (int w = 0; w < NW; w++)
            zs[w] += __shfl_down_sync(0xffffffffu, zs[w], off);
    __syncthreads();                       // all psi reads done; reuse as scratch
    float* red = (float*)psi;
    const int NWARP = NT/32;
    int lane = t & 31, wid = t >> 5;
    if (lane == 0){
        #pragma unroll
        for (int w = 0; w < NW; w++) red[w*NWARP + wid] = zs[w];
    }
    __syncthreads();
    if (t == 0){
        float acc = __ldg(hb);
        #pragma unroll
        for (int w = 0; w < NW; w++){
            float f = 0.f;
            #pragma unroll
            for (int r = 0; r < NWARP; r++) f += red[w*NWARP + r];
            acc += f * __ldg(hw + w);
        }
        out[b] = acc;
    }
}

// ---------------- launch ----------------

extern "C" void kernel_launch(void* const* d_in, const int* in_sizes, int n_in,
                              void* d_out, int out_size)
{
    const float* sr = (const float*)d_in[0];
    const float* si = (const float*)d_in[1];
    const float* vp = (const float*)d_in[2];
    const float* hw = (const float*)d_in[3];
    const float* hb = (const float*)d_in[4];
    float* out = (float*)d_out;

    const int SMEM = DIM*sizeof(float2) + 576*sizeof(float4) + 3*NW*sizeof(float2);

    cudaFuncSetAttribute(qsim_kernel, cudaFuncAttributeMaxDynamicSharedMemorySize, SMEM);

    setup_all<<<1, 576>>>(vp);

    int B = in_sizes[0] / DIM;
    qsim_kernel<<<B, NT, SMEM>>>(sr, si, hw, hb, out);
}

// round 9
// speedup vs baseline: 1.0264x; 1.0264x over previous
#include <cuda_runtime.h>

// QuantumRegression: 1024 x 14-qubit statevector sim, 3 layers (Rot per wire + CNOT ring),
// <Z_w> features, linear head.
//
// R9: ZYZ with forward-merged diagonals. Exit diag of pass A merges into pass B's entry,
// exit of B into C's entry — precombined into smem tables (setup kernel), so each pass
// applies ONE LDS.128 + ONE cmult per amp, then real RY rotations. C keeps a small exit
// table (layers 0,1); final layer's exit diag dropped (|amp|^2 phase-invariant).
// Frame-tracked CNOT perms, XOR-staggered pass C, Walsh measurement. NT=512.

#define NW   14
#define DIM  16384
#define NT   512

typedef unsigned long long u64;

// table segments (float4 {c,c,-s,s} entries)
#define OFF_A   0          // 3 x 32   : entry A  (delta wires 0..4   over bits 13..9)
#define OFF_B   96         // 3 x 1024 : entry B  = exitA(beta w0..4, bits13..9) * delta(w5..9, bits8..4)
#define OFF_C   3168       // 3 x 512  : entry C  = exitB(beta w5..9, bits8..4) * delta(w10..13, bits3..0)
#define OFF_BC  4704       // 2 x 16   : exit C   (beta wires 10..13 over bits 3..0), layers 0,1
#define NTAB    4736

__device__ float  g_beta[3*NW], g_delta[3*NW];
__device__ float2 g_rot[3*NW];          // per-wire (cos g/2, sin g/2)
__device__ float4 g_tab[NTAB];

// ---------------- setup 1: ZYZ decomposition ----------------

struct cpx { float re, im; };
__device__ __forceinline__ cpx cmul(cpx a, cpx b){
    cpx r; r.re = a.re*b.re - a.im*b.im; r.im = a.re*b.im + a.im*b.re; return r;
}

__device__ void rotmat(const float* p, cpx U[2][2]){
    float cx = cosf(0.5f*p[0]), sx = sinf(0.5f*p[0]);
    float cy = cosf(0.5f*p[1]), sy = sinf(0.5f*p[1]);
    float cz = cosf(0.5f*p[2]), sz = sinf(0.5f*p[2]);
    cpx r00 = { cy*cx,  sy*sx};
    cpx r01 = {-sy*cx, -cy*sx};
    cpx r10 = { sy*cx, -cy*sx};
    cpx r11 = { cy*cx, -sy*sx};
    cpx e0 = {cz, -sz}, e1 = {cz, sz};
    U[0][0] = cmul(e0, r00); U[0][1] = cmul(e0, r01);
    U[1][0] = cmul(e1, r10); U[1][1] = cmul(e1, r11);
}

__global__ void setup_decomp(const float* __restrict__ vp){
    int t = threadIdx.x;
    if (t >= 3*NW) return;
    cpx U[2][2]; rotmat(vp + t*3, U);
    float na = hypotf(U[0][0].re, U[0][0].im);
    float nc = hypotf(U[1][0].re, U[1][0].im);
    float n  = hypotf(na, nc);
    g_rot[t] = make_float2(na/n, nc/n);     // (cos g/2, sin g/2), both >= 0
    float beta, delta;
    if (nc > 1e-6f && na > 1e-6f){
        float aa = atan2f(U[0][0].im, U[0][0].re);
        float ac = atan2f(U[1][0].im, U[1][0].re);
        float ad = atan2f(U[1][1].im, U[1][1].re);
        beta = ac - aa; delta = ad - ac;
    } else if (nc <= 1e-6f){                // gamma ~ 0: U = e^{ia} RZ(beta)
        delta = 0.f;
        beta = atan2f(U[1][1].im, U[1][1].re) - atan2f(U[0][0].im, U[0][0].re);
    } else {                                // gamma ~ pi
        delta = 0.f;
        beta = atan2f(U[1][0].im, U[1][0].re) - atan2f(-U[0][1].im, -U[0][1].re);
    }
    g_beta[t] = beta; g_delta[t] = delta;
}

// ---------------- setup 2: combined diagonal tables ----------------

__device__ __forceinline__ float angsum(const float* a, int wfirst, int bits, int nb, int step){
    // sum over k<nb of +-a[wfirst - k]/2, sign from bit k of `bits`
    float s = 0.f;
    for (int k = 0; k < nb; k++){
        float h = 0.5f * a[wfirst - k];
        s += ((bits >> k) & 1) ? h : -h;
    }
    (void)step;
    return s;
}

__global__ void setup_tables(void){
    int idx = blockIdx.x * blockDim.x + threadIdx.x;
    if (idx >= NTAB) return;
    float ang = 0.f;
    if (idx < OFF_B){                                     // entry A
        int r = idx - OFF_A; int l = r >> 5, f = r & 31;
        ang = angsum(g_delta, l*NW + 4, f, 5, 0);
    } else if (idx < OFF_C){                              // entry B (combined)
        int r = idx - OFF_B; int l = r >> 10; r &= 1023;
        int h = r >> 5, f = r & 31;
        ang = angsum(g_beta,  l*NW + 4, h, 5, 0)
            + angsum(g_delta, l*NW + 9, f, 5, 0);
    } else if (idx < OFF_BC){                             // entry C (combined)
        int r = idx - OFF_C; int l = r >> 9; r &= 511;
        int h = r >> 4, m = r & 15;
        ang = angsum(g_beta,  l*NW + 9,  h, 5, 0)
            + angsum(g_delta, l*NW + 13, m, 4, 0);
    } else {                                              // exit C, layers 0,1
        int r = idx - OFF_BC; int l = r >> 4, m = r & 15;
        ang = angsum(g_beta, l*NW + 13, m, 4, 0);
    }
    float sp, cp; sincosf(ang, &sp, &cp);
    g_tab[idx] = make_float4(cp, cp, -sp, sp);
}

// ---------------- packed f32x2 helpers ----------------

__device__ __forceinline__ u64 pk2(float lo, float hi){
    u64 r; asm("mov.b64 %0, {%1,%2};" : "=l"(r) : "f"(lo), "f"(hi)); return r;
}
__device__ __forceinline__ void upk2(u64 v, float& lo, float& hi){
    asm("mov.b64 {%0,%1}, %2;" : "=f"(lo), "=f"(hi) : "l"(v));
}
__device__ __forceinline__ u64 swp2(u64 v){
    u64 r;
    asm("{ .reg .b32 a,b; mov.b64 {a,b}, %1; mov.b64 %0, {b,a}; }" : "=l"(r) : "l"(v));
    return r;
}
__device__ __forceinline__ u64 f2(u64 a, u64 b, u64 c){
    u64 r; asm("fma.rn.f32x2 %0, %1, %2, %3;" : "=l"(r) : "l"(a), "l"(b), "l"(c)); return r;
}
__device__ __forceinline__ u64 m2(u64 a, u64 b){
    u64 r; asm("mul.rn.f32x2 %0, %1, %2;" : "=l"(r) : "l"(a), "l"(b)); return r;
}

// amp *= phase(q)   q = {c,c,-s,s}
__device__ __forceinline__ u64 dmul(u64 amp, float4 q){
    u64 uu = pk2(q.x, q.y), nn = pk2(q.z, q.w);
    return f2(uu, amp, m2(nn, swp2(amp)));
}

// NB real RY rotations on bits NB-1..0 of a 2^NB-amp tile; bit k <-> wire w0-k.
// u-bit set => logical 0/1 roles swapped => s -> -s.
template<int NB>
__device__ __forceinline__ void rotTile(u64* amp, const float2* rot, int w0, int u){
    #pragma unroll
    for (int k = NB-1; k >= 0; k--){
        float2 cs = rot[w0 - k];
        float s = ((u >> k) & 1) ? -cs.y : cs.y;
        u64 cc = pk2(cs.x, cs.x), ss = pk2(s, s), ns = pk2(-s, -s);
        const int bit = 1 << k;
        #pragma unroll
        for (int p = 0; p < (1 << NB); p++)
            if (!(p & bit)){
                u64 v0 = amp[p], v1 = amp[p | bit];
                amp[p]       = f2(cc, v0, m2(ns, v1));
                amp[p | bit] = f2(cc, v1, m2(ss, v0));
            }
    }
}

// ---------------- CNOT-ring permutation (GF2 linear, constexpr-foldable) ----------------
__host__ __device__ __forceinline__ constexpr int cpfwd(int i){
    int y = i;
    y ^= y >> 1; y ^= y >> 2; y ^= y >> 4; y ^= y >> 8;
    return (y & 0x1FFF) ^ ((((y ^ (i >> 13)) & 1) << 13));
}
__host__ __device__ __forceinline__ constexpr int cpinv(int o){
    int t = o ^ (o >> 1);
    return (t & 0x1FFF) ^ (o & 0x2000) ^ ((o & 1) ? 0x3000 : 0);
}
template<int L>
__host__ __device__ __forceinline__ constexpr int pinvL(int x){
    return (L == 0) ? x : (L == 1) ? cpinv(x) : cpinv(cpinv(x));
}

// ---------------- passes ----------------

// pass A: logical bits 13..9 (wires 0..4), layer L. One 32-amp tile per thread.
template<int L>
__device__ __forceinline__ void passA(float2* psi, const float4* stab, const float2* srot, int t){
    const float4* tab = stab + OFF_A + L*32;
    int base = pinvL<L>(t);
    u64 amp[32];
    #pragma unroll
    for (int f = 0; f < 32; f++){
        float2 a = psi[base ^ pinvL<L>(f << 9)];
        amp[f] = dmul(pk2(a.x, a.y), tab[f]);
    }
    rotTile<5>(amp, srot, L*NW + 4, 0);
    #pragma unroll
    for (int f = 0; f < 32; f++){
        float xx, yy; upk2(amp[f], xx, yy);
        psi[base ^ pinvL<L>(f << 9)] = make_float2(xx, yy);
    }
}

// pass B: logical bits 8..4 (wires 5..9), layer L; entry = exitA * entryB combined table.
template<int L>
__device__ __forceinline__ void passB(float2* psi, const float4* stab, const float2* srot, int t){
    const float4* tab = stab + OFF_B + L*1024 + ((t >> 4) << 5);
    int x = ((t >> 4) << 9) | (t & 15);
    int base = pinvL<L>(x);
    u64 amp[32];
    #pragma unroll
    for (int f = 0; f < 32; f++){
        float2 a = psi[base ^ pinvL<L>(f << 4)];
        amp[f] = dmul(pk2(a.x, a.y), tab[f]);
    }
    rotTile<5>(amp, srot, L*NW + 9, 0);
    #pragma unroll
    for (int f = 0; f < 32; f++){
        float xx, yy; upk2(amp[f], xx, yy);
        psi[base ^ pinvL<L>(f << 4)] = make_float2(xx, yy);
    }
}

// stagger offset u for C passes: u = A_L^{-1}((lane&15) ^ base_low4)
template<int L>
__device__ __forceinline__ int p3stagger(int t){
    int r4 = t & 15;
    if (L == 0) return r4;
    if (L == 1){ int v = r4 ^ ((t & 1) << 3); return (v ^ (v>>1) ^ (v>>2) ^ (v>>3)) & 15; }
    int v = r4 ^ ((t & 3) << 2); return (v ^ (v >> 2)) & 15;
}

// pass C: logical bits 3..0 (wires 10..13), layer L; entry = exitB * entryC combined.
// MEAS folds P^3 measurement; exit diag applied only for layers 0,1.
template<int L, bool MEAS>
__device__ __forceinline__ void passC(float2* psi, const float4* stab, const float2* srot,
                                      int t, float* zs){
    const float4* tabC = stab + OFF_C + L*512;
    const float4* tabX = stab + OFF_BC + L*16;
    const int u = p3stagger<L>(t);
    const int uoff = pinvL<L>(u);
    #pragma unroll 1
    for (int tt = 0; tt < DIM/16/NT; tt++){
        int y = t + NT*tt;                        // 10-bit tile index (logical bits 13..4)
        int base = pinvL<L>(y << 4) ^ uoff;
        int row = (y & 31) << 4;
        u64 amp[16];
        #pragma unroll
        for (int m = 0; m < 16; m++){
            float2 a = psi[base ^ pinvL<L>(m)];
            amp[m] = dmul(pk2(a.x, a.y), tabC[row | (m ^ u)]);
        }
        rotTile<4>(amp, srot, L*NW + 13, u);
        if (!MEAS){
            #pragma unroll
            for (int m = 0; m < 16; m++){
                u64 o = dmul(amp[m], tabX[m ^ u]);
                float xx, yy; upk2(o, xx, yy);
                psi[base ^ pinvL<L>(m)] = make_float2(xx, yy);
            }
        } else {
            // logical o = cpfwd((y<<4) ^ u ^ m); cpfwd(m) sign bits live in o bits 3..0,13
            int obase = cpfwd((y << 4) ^ u);
            float pr[16];
            #pragma unroll
            for (int m = 0; m < 16; m++){
                float xx, yy; upk2(amp[m], xx, yy);
                pr[m] = xx*xx + yy*yy;
            }
            // partial Walsh butterfly over m bits b0..b3:
            //   o bit0 = b0^b1^b2^b3 (also bit13), bit1 = b1^b2^b3, bit2 = b2^b3, bit3 = b3
            float P[8], Mv[8];
            #pragma unroll
            for (int j = 0; j < 8; j++){ P[j] = pr[2*j] + pr[2*j+1]; Mv[j] = pr[2*j] - pr[2*j+1]; }
            float Spar = Mv[0]-Mv[1]-Mv[2]+Mv[3]-Mv[4]+Mv[5]+Mv[6]-Mv[7];
            float PP[4], PM[4];
            #pragma unroll
            for (int k = 0; k < 4; k++){ PP[k] = P[2*k] + P[2*k+1]; PM[k] = P[2*k] - P[2*k+1]; }
            float S123 = PM[0]-PM[1]-PM[2]+PM[3];
            float PPP0 = PP[0]+PP[1], PPP1 = PP[2]+PP[3];
            float S23  = (PP[0]-PP[1]) - (PP[2]-PP[3]);
            float T    = PPP0 + PPP1;
            float S3   = PPP0 - PPP1;
            #pragma unroll
            for (int w = 1; w <= 9; w++){
                unsigned msk = ((unsigned)obase << (18 + w)) & 0x80000000u;
                zs[w] += __uint_as_float(__float_as_uint(T) ^ msk);
            }
            zs[0]  += __uint_as_float(__float_as_uint(Spar) ^ (((unsigned)obase << 18) & 0x80000000u)); // bit13
            zs[13] += __uint_as_float(__float_as_uint(Spar) ^ (((unsigned)obase << 31) & 0x80000000u)); // bit0
            zs[12] += __uint_as_float(__float_as_uint(S123) ^ (((unsigned)obase << 30) & 0x80000000u)); // bit1
            zs[11] += __uint_as_float(__float_as_uint(S23)  ^ (((unsigned)obase << 29) & 0x80000000u)); // bit2
            zs[10] += __uint_as_float(__float_as_uint(S3)   ^ (((unsigned)obase << 28) & 0x80000000u)); // bit3
        }
    }
}

// ---------------- main kernel ----------------

__global__ void __launch_bounds__(NT, 1)
qsim_kernel(const float* __restrict__ sr, const float* __restrict__ si,
            const float* __restrict__ hw, const float* __restrict__ hb,
            float* __restrict__ out)
{
    extern __shared__ float2 sm[];
    float2* psi = sm;
    float4* stab = reinterpret_cast<float4*>(sm + DIM);               // NTAB float4
    float2* srot = reinterpret_cast<float2*>(stab + NTAB);            // 42 float2
    const int t = threadIdx.x;
    const int b = blockIdx.x;

    // stage tables into smem
    #pragma unroll 1
    for (int i = t; i < NTAB; i += NT) stab[i] = g_tab[i];
    if (t < 3*NW) srot[t] = g_rot[t];
    __syncthreads();

    // ---- layer 0 pass A fused with global load ----
    {
        const float* srb = sr + (size_t)b * DIM;
        const float* sib = si + (size_t)b * DIM;
        const float4* tab = stab + OFF_A;
        u64 amp[32];
        #pragma unroll
        for (int f = 0; f < 32; f++){
            float re = __ldg(srb + (f << 9) + t);
            float im = __ldg(sib + (f << 9) + t);
            amp[f] = dmul(pk2(re, im), tab[f]);
        }
        rotTile<5>(amp, srot, 4, 0);
        #pragma unroll
        for (int f = 0; f < 32; f++){
            float x, y; upk2(amp[f], x, y);
            psi[(f << 9) + t] = make_float2(x, y);
        }
    }
    __syncthreads();
    passB<0>(psi, stab, srot, t);            __syncthreads();
    passC<0,false>(psi, stab, srot, t, 0);   __syncthreads();

    passA<1>(psi, stab, srot, t);            __syncthreads();
    passB<1>(psi, stab, srot, t);            __syncthreads();
    passC<1,false>(psi, stab, srot, t, 0);   __syncthreads();

    passA<2>(psi, stab, srot, t);            __syncthreads();
    passB<2>(psi, stab, srot, t);            __syncthreads();

    // ---- layer 2 pass C + measurement (P^3 folded; exit diag dropped) ----
    float zs[NW];
    #pragma unroll
    for (int w = 0; w < NW; w++) zs[w] = 0.f;
    passC<2,true>(psi, stab, srot, t, zs);

    // warp reduce
    #pragma unroll
    for (int off = 16; off > 0; off >>= 1)
        #pragma unroll
        for (int w = 0; w < NW; w++)
            zs[w] += __shfl_down_sync(0xffffffffu, zs[w], off);
    __syncthreads();                       // all psi reads done; reuse as scratch
    float* red = (float*)psi;
    const int NWARP = NT/32;
    int lane = t & 31, wid = t >> 5;
    if (lane == 0){
        #pragma unroll
        for (int w = 0; w < NW; w++) red[w*NWARP + wid] = zs[w];
    }
    __syncthreads();
    if (t == 0){
        float acc = __ldg(hb);
        #pragma unroll
        for (int w = 0; w < NW; w++){
            float f = 0.f;
            #pragma unroll
            for (int r = 0; r < NWARP; r++) f += red[w*NWARP + r];
            acc += f * __ldg(hw + w);
        }
        out[b] = acc;
    }
}

// ---------------- launch ----------------

extern "C" void kernel_launch(void* const* d_in, const int* in_sizes, int n_in,
                              void* d_out, int out_size)
{
    const float* sr = (const float*)d_in[0];
    const float* si = (const float*)d_in[1];
    const float* vp = (const float*)d_in[2];
    const float* hw = (const float*)d_in[3];
    const float* hb = (const float*)d_in[4];
    float* out = (float*)d_out;

    const int SMEM = DIM*sizeof(float2) + NTAB*sizeof(float4) + 3*NW*sizeof(float2);

    cudaFuncSetAttribute(qsim_kernel, cudaFuncAttributeMaxDynamicSharedMemorySize, SMEM);

    setup_decomp<<<1, 64>>>(vp);
    setup_tables<<<5, 1024>>>();

    int B = in_sizes[0] / DIM;
    qsim_kernel<<<B, NT, SMEM>>>(sr, si, hw, hb, out);
}

// round 10
// speedup vs baseline: 1.1712x; 1.1411x over previous
#include <cuda_runtime.h>

// QuantumRegression: 1024 x 14-qubit statevector sim, 3 layers (Rot per wire + CNOT ring),
// <Z_w> features, linear head.
//
// R10: ZYZ with FULL forward deferral of exit diagonals across the frame change:
//   beta_A(l), beta_B(l)  -> entry-A(l+1) table  T_A[l+1] (2048: bits t8..4, f, t0)
//   beta_C(l)             -> entry-B(l+1) table  T_B[l+1] (512: f, t&15)
//   layer-2 betas         -> dropped (diagonal after last rotation; |amp|^2 kills phases)
// Every pass = one dmul per amp (entry table) + real RY rotations. Single setup kernel.
// Frame-tracked CNOT perms, XOR-staggered pass C, Walsh measurement. NT=512.

#define NW   14
#define DIM  16384
#define NT   512

typedef unsigned long long u64;

// table offsets (float4 {c,c,-s,s})
#define OFF_A0  0        // 32    : layer0 entry A (deltas only), idx f
#define OFF_A1  32       // 2048  : layer1 entry A, idx (h<<6)|(f<<1)|t0
#define OFF_A2  2080     // 2048  : layer2 entry A
#define OFF_B0  4128     // 32    : layer0 entry B, idx f
#define OFF_B1  4160     // 512   : layer1 entry B, idx (f<<4)|q
#define OFF_B2  4672     // 512   : layer2 entry B
#define OFF_C   5184     // 3x16  : entry C per layer, idx m^u
#define NTAB    5232

__device__ float2 g_rot[3*NW];          // per-wire (cos g/2, sin g/2)
__device__ float4 g_tab[NTAB];

// ---------------- setup: ZYZ decomposition + deferred-diagonal tables ----------------

struct cpx { float re, im; };
__device__ __forceinline__ cpx cmul(cpx a, cpx b){
    cpx r; r.re = a.re*b.re - a.im*b.im; r.im = a.re*b.im + a.im*b.re; return r;
}

__device__ void rotmat(const float* p, cpx U[2][2]){
    float cx = cosf(0.5f*p[0]), sx = sinf(0.5f*p[0]);
    float cy = cosf(0.5f*p[1]), sy = sinf(0.5f*p[1]);
    float cz = cosf(0.5f*p[2]), sz = sinf(0.5f*p[2]);
    cpx r00 = { cy*cx,  sy*sx};
    cpx r01 = {-sy*cx, -cy*sx};
    cpx r10 = { sy*cx, -cy*sx};
    cpx r11 = { cy*cx, -sy*sx};
    cpx e0 = {cz, -sz}, e1 = {cz, sz};
    U[0][0] = cmul(e0, r00); U[0][1] = cmul(e0, r01);
    U[1][0] = cmul(e1, r10); U[1][1] = cmul(e1, r11);
}

// sum over k<nb of +-a[w0 - k]/2, sign from bit k of `bits` (set -> +)
__device__ __forceinline__ float angsum(const float* a, int w0, int bits, int nb){
    float s = 0.f;
    for (int k = 0; k < nb; k++){
        float h = 0.5f * a[w0 - k];
        s += ((bits >> k) & 1) ? h : -h;
    }
    return s;
}

__global__ void setup_all(const float* __restrict__ vp){
    __shared__ float sb[3*NW], sd[3*NW];
    int t = threadIdx.x;
    if (t < 3*NW){
        cpx U[2][2]; rotmat(vp + t*3, U);
        float na = hypotf(U[0][0].re, U[0][0].im);
        float nc = hypotf(U[1][0].re, U[1][0].im);
        float n  = hypotf(na, nc);
        g_rot[t] = make_float2(na/n, nc/n);     // (cos g/2, sin g/2), both >= 0
        float beta, delta;
        if (nc > 1e-6f && na > 1e-6f){
            float aa = atan2f(U[0][0].im, U[0][0].re);
            float ac = atan2f(U[1][0].im, U[1][0].re);
            float ad = atan2f(U[1][1].im, U[1][1].re);
            beta = ac - aa; delta = ad - ac;
        } else if (nc <= 1e-6f){                // gamma ~ 0
            delta = 0.f;
            beta = atan2f(U[1][1].im, U[1][1].re) - atan2f(U[0][0].im, U[0][0].re);
        } else {                                // gamma ~ pi
            delta = 0.f;
            beta = atan2f(U[1][0].im, U[1][0].re) - atan2f(-U[0][1].im, -U[0][1].re);
        }
        sb[t] = beta; sd[t] = delta;
    }
    __syncthreads();
    for (int idx = t; idx < NTAB; idx += blockDim.x){
        float ang;
        if (idx < OFF_A1){                       // layer0 entry A: deltas only
            ang = angsum(sd, 0*NW + 4, idx, 5);
        } else if (idx < OFF_B0){                // entry A layers 1,2
            int l = (idx < OFF_A2) ? 1 : 2;
            int r = idx - ((l == 1) ? OFF_A1 : OFF_A2);
            int h = r >> 6, f = (r >> 1) & 31, t0 = r & 1;
            // betaA(l-1): sign word over wires 4..0 from pinv bit formulas
            int sA = (f ^ (f >> 1)) ^ (t0 ? 0x18 : 0);
            // betaB(l-1): over wires 9..5
            int sB = (h ^ (h >> 1)) ^ ((f & 1) ? 0x10 : 0);
            ang = angsum(sd, l*NW + 4, f, 5)
                + angsum(sb, (l-1)*NW + 4, sA, 5)
                + angsum(sb, (l-1)*NW + 9, sB, 5);
        } else if (idx < OFF_B1){                // layer0 entry B: deltas only
            ang = angsum(sd, 0*NW + 9, idx - OFF_B0, 5);
        } else if (idx < OFF_C){                 // entry B layers 1,2
            int l = (idx < OFF_B2) ? 1 : 2;
            int r = idx - ((l == 1) ? OFF_B1 : OFF_B2);
            int f = r >> 4, q = r & 15;
            // betaC(l-1): over wires 13..10
            int sC = (q ^ (q >> 1)) ^ ((f & 1) ? 8 : 0);
            ang = angsum(sd, l*NW + 9, f, 5)
                + angsum(sb, (l-1)*NW + 13, sC, 4);
        } else {                                 // entry C per layer: deltas only
            int r = idx - OFF_C; int l = r >> 4, m = r & 15;
            ang = angsum(sd, l*NW + 13, m, 4);
        }
        float sp, cp; sincosf(ang, &sp, &cp);
        g_tab[idx] = make_float4(cp, cp, -sp, sp);
    }
}

// ---------------- packed f32x2 helpers ----------------

__device__ __forceinline__ u64 pk2(float lo, float hi){
    u64 r; asm("mov.b64 %0, {%1,%2};" : "=l"(r) : "f"(lo), "f"(hi)); return r;
}
__device__ __forceinline__ void upk2(u64 v, float& lo, float& hi){
    asm("mov.b64 {%0,%1}, %2;" : "=f"(lo), "=f"(hi) : "l"(v));
}
__device__ __forceinline__ u64 swp2(u64 v){
    u64 r;
    asm("{ .reg .b32 a,b; mov.b64 {a,b}, %1; mov.b64 %0, {b,a}; }" : "=l"(r) : "l"(v));
    return r;
}
__device__ __forceinline__ u64 f2(u64 a, u64 b, u64 c){
    u64 r; asm("fma.rn.f32x2 %0, %1, %2, %3;" : "=l"(r) : "l"(a), "l"(b), "l"(c)); return r;
}
__device__ __forceinline__ u64 m2(u64 a, u64 b){
    u64 r; asm("mul.rn.f32x2 %0, %1, %2;" : "=l"(r) : "l"(a), "l"(b)); return r;
}

// amp *= phase(q)   q = {c,c,-s,s}
__device__ __forceinline__ u64 dmul(u64 amp, float4 q){
    u64 uu = pk2(q.x, q.y), nn = pk2(q.z, q.w);
    return f2(uu, amp, m2(nn, swp2(amp)));
}

// NB real RY rotations on bits NB-1..0 of a 2^NB-amp tile; bit k <-> wire w0-k.
// u-bit set => logical 0/1 roles swapped => s -> -s.
template<int NB>
__device__ __forceinline__ void rotTile(u64* amp, const float2* rot, int w0, int u){
    #pragma unroll
    for (int k = NB-1; k >= 0; k--){
        float2 cs = rot[w0 - k];
        float s = ((u >> k) & 1) ? -cs.y : cs.y;
        u64 cc = pk2(cs.x, cs.x), ss = pk2(s, s), ns = pk2(-s, -s);
        const int bit = 1 << k;
        #pragma unroll
        for (int p = 0; p < (1 << NB); p++)
            if (!(p & bit)){
                u64 v0 = amp[p], v1 = amp[p | bit];
                amp[p]       = f2(cc, v0, m2(ns, v1));
                amp[p | bit] = f2(cc, v1, m2(ss, v0));
            }
    }
}

// ---------------- CNOT-ring permutation (GF2 linear, constexpr-foldable) ----------------
__host__ __device__ __forceinline__ constexpr int cpfwd(int i){
    int y = i;
    y ^= y >> 1; y ^= y >> 2; y ^= y >> 4; y ^= y >> 8;
    return (y & 0x1FFF) ^ ((((y ^ (i >> 13)) & 1) << 13));
}
__host__ __device__ __forceinline__ constexpr int cpinv(int o){
    int t = o ^ (o >> 1);
    return (t & 0x1FFF) ^ (o & 0x2000) ^ ((o & 1) ? 0x3000 : 0);
}
template<int L>
__host__ __device__ __forceinline__ constexpr int pinvL(int x){
    return (L == 0) ? x : (L == 1) ? cpinv(x) : cpinv(cpinv(x));
}

// ---------------- passes ----------------

// pass A (layers 1,2): logical bits 13..9; entry table folds deltaA(L) + betaA/B(L-1).
template<int L>
__device__ __forceinline__ void passA(float2* psi, const float4* stab, const float2* srot, int t){
    const float4* tab = stab + ((L == 1) ? OFF_A1 : OFF_A2);
    const int ib = (((t >> 4) & 31) << 6) | (t & 1);
    int base = pinvL<L>(t);
    u64 amp[32];
    #pragma unroll
    for (int f = 0; f < 32; f++){
        float2 a = psi[base ^ pinvL<L>(f << 9)];
        amp[f] = dmul(pk2(a.x, a.y), tab[ib | (f << 1)]);
    }
    rotTile<5>(amp, srot, L*NW + 4, 0);
    #pragma unroll
    for (int f = 0; f < 32; f++){
        float xx, yy; upk2(amp[f], xx, yy);
        psi[base ^ pinvL<L>(f << 9)] = make_float2(xx, yy);
    }
}

// pass B: logical bits 8..4; entry table folds deltaB(L) (+ betaC(L-1) for L>=1).
template<int L>
__device__ __forceinline__ void passB(float2* psi, const float4* stab, const float2* srot, int t){
    const float4* tab = stab + ((L == 0) ? OFF_B0 : (L == 1) ? OFF_B1 : OFF_B2);
    const int q = t & 15;
    int x = ((t >> 4) << 9) | q;
    int base = pinvL<L>(x);
    u64 amp[32];
    #pragma unroll
    for (int f = 0; f < 32; f++){
        float2 a = psi[base ^ pinvL<L>(f << 4)];
        amp[f] = dmul(pk2(a.x, a.y), (L == 0) ? tab[f] : tab[(f << 4) | q]);
    }
    rotTile<5>(amp, srot, L*NW + 9, 0);
    #pragma unroll
    for (int f = 0; f < 32; f++){
        float xx, yy; upk2(amp[f], xx, yy);
        psi[base ^ pinvL<L>(f << 4)] = make_float2(xx, yy);
    }
}

// stagger offset u for C passes: u = A_L^{-1}((lane&15) ^ base_low4)
template<int L>
__device__ __forceinline__ int p3stagger(int t){
    int r4 = t & 15;
    if (L == 0) return r4;
    if (L == 1){ int v = r4 ^ ((t & 1) << 3); return (v ^ (v>>1) ^ (v>>2) ^ (v>>3)) & 15; }
    int v = r4 ^ ((t & 3) << 2); return (v ^ (v >> 2)) & 15;
}

// pass C: logical bits 3..0; entry = deltaC(L) (16-entry table). No exit work (deferred
// or dropped). MEAS folds P^3 measurement with partial Walsh butterfly.
template<int L, bool MEAS>
__device__ __forceinline__ void passC(float2* psi, const float4* stab, const float2* srot,
                                      int t, float* zs){
    const float4* tabC = stab + OFF_C + L*16;
    const int u = p3stagger<L>(t);
    const int uoff = pinvL<L>(u);
    #pragma unroll 1
    for (int tt = 0; tt < DIM/16/NT; tt++){
        int y = t + NT*tt;                        // 10-bit tile index (logical bits 13..4)
        int base = pinvL<L>(y << 4) ^ uoff;
        u64 amp[16];
        #pragma unroll
        for (int m = 0; m < 16; m++){
            float2 a = psi[base ^ pinvL<L>(m)];
            amp[m] = dmul(pk2(a.x, a.y), tabC[m ^ u]);
        }
        rotTile<4>(amp, srot, L*NW + 13, u);
        if (!MEAS){
            #pragma unroll
            for (int m = 0; m < 16; m++){
                float xx, yy; upk2(amp[m], xx, yy);
                psi[base ^ pinvL<L>(m)] = make_float2(xx, yy);
            }
        } else {
            // logical o = cpfwd((y<<4) ^ u ^ m); cpfwd(m) sign bits live in o bits 3..0,13
            int obase = cpfwd((y << 4) ^ u);
            float pr[16];
            #pragma unroll
            for (int m = 0; m < 16; m++){
                float xx, yy; upk2(amp[m], xx, yy);
                pr[m] = xx*xx + yy*yy;
            }
            // partial Walsh butterfly over m bits b0..b3:
            //   o bit0 = b0^b1^b2^b3 (also bit13), bit1 = b1^b2^b3, bit2 = b2^b3, bit3 = b3
            float P[8], Mv[8];
            #pragma unroll
            for (int j = 0; j < 8; j++){ P[j] = pr[2*j] + pr[2*j+1]; Mv[j] = pr[2*j] - pr[2*j+1]; }
            float Spar = Mv[0]-Mv[1]-Mv[2]+Mv[3]-Mv[4]+Mv[5]+Mv[6]-Mv[7];
            float PP[4], PM[4];
            #pragma unroll
            for (int k = 0; k < 4; k++){ PP[k] = P[2*k] + P[2*k+1]; PM[k] = P[2*k] - P[2*k+1]; }
            float S123 = PM[0]-PM[1]-PM[2]+PM[3];
            float PPP0 = PP[0]+PP[1], PPP1 = PP[2]+PP[3];
            float S23  = (PP[0]-PP[1]) - (PP[2]-PP[3]);
            float T    = PPP0 + PPP1;
            float S3   = PPP0 - PPP1;
            #pragma unroll
            for (int w = 1; w <= 9; w++){
                unsigned msk = ((unsigned)obase << (18 + w)) & 0x80000000u;
                zs[w] += __uint_as_float(__float_as_uint(T) ^ msk);
            }
            zs[0]  += __uint_as_float(__float_as_uint(Spar) ^ (((unsigned)obase << 18) & 0x80000000u)); // bit13
            zs[13] += __uint_as_float(__float_as_uint(Spar) ^ (((unsigned)obase << 31) & 0x80000000u)); // bit0
            zs[12] += __uint_as_float(__float_as_uint(S123) ^ (((unsigned)obase << 30) & 0x80000000u)); // bit1
            zs[11] += __uint_as_float(__float_as_uint(S23)  ^ (((unsigned)obase << 29) & 0x80000000u)); // bit2
            zs[10] += __uint_as_float(__float_as_uint(S3)   ^ (((unsigned)obase << 28) & 0x80000000u)); // bit3
        }
    }
}

// ---------------- main kernel ----------------

__global__ void __launch_bounds__(NT, 1)
qsim_kernel(const float* __restrict__ sr, const float* __restrict__ si,
            const float* __restrict__ hw, const float* __restrict__ hb,
            float* __restrict__ out)
{
    extern __shared__ float2 sm[];
    float2* psi = sm;
    float4* stab = reinterpret_cast<float4*>(sm + DIM);               // NTAB float4
    float2* srot = reinterpret_cast<float2*>(stab + NTAB);            // 42 float2
    const int t = threadIdx.x;
    const int b = blockIdx.x;

    // stage tables into smem
    #pragma unroll 1
    for (int i = t; i < NTAB; i += NT) stab[i] = g_tab[i];
    if (t < 3*NW) srot[t] = g_rot[t];
    __syncthreads();

    // ---- layer 0 pass A fused with global load ----
    {
        const float* srb = sr + (size_t)b * DIM;
        const float* sib = si + (size_t)b * DIM;
        const float4* tab = stab + OFF_A0;
        u64 amp[32];
        #pragma unroll
        for (int f = 0; f < 32; f++){
            float re = __ldg(srb + (f << 9) + t);
            float im = __ldg(sib + (f << 9) + t);
            amp[f] = dmul(pk2(re, im), tab[f]);
        }
        rotTile<5>(amp, srot, 4, 0);
        #pragma unroll
        for (int f = 0; f < 32; f++){
            float x, y; upk2(amp[f], x, y);
            psi[(f << 9) + t] = make_float2(x, y);
        }
    }
    __syncthreads();
    passB<0>(psi, stab, srot, t);            __syncthreads();
    passC<0,false>(psi, stab, srot, t, 0);   __syncthreads();

    passA<1>(psi, stab, srot, t);            __syncthreads();
    passB<1>(psi, stab, srot, t);            __syncthreads();
    passC<1,false>(psi, stab, srot, t, 0);   __syncthreads();

    passA<2>(psi, stab, srot, t);            __syncthreads();
    passB<2>(psi, stab, srot, t);            __syncthreads();

    // ---- layer 2 pass C + measurement (P^3 folded; all exit diagonals dropped) ----
    float zs[NW];
    #pragma unroll
    for (int w = 0; w < NW; w++) zs[w] = 0.f;
    passC<2,true>(psi, stab, srot, t, zs);

    // warp reduce
    #pragma unroll
    for (int off = 16; off > 0; off >>= 1)
        #pragma unroll
        for (int w = 0; w < NW; w++)
            zs[w] += __shfl_down_sync(0xffffffffu, zs[w], off);
    __syncthreads();                       // all psi reads done; reuse as scratch
    float* red = (float*)psi;
    const int NWARP = NT/32;
    int lane = t & 31, wid = t >> 5;
    if (lane == 0){
        #pragma unroll
        for (int w = 0; w < NW; w++) red[w*NWARP + wid] = zs[w];
    }
    __syncthreads();
    if (t == 0){
        float acc = __ldg(hb);
        #pragma unroll
        for (int w = 0; w < NW; w++){
            float f = 0.f;
            #pragma unroll
            for (int r = 0; r < NWARP; r++) f += red[w*NWARP + r];
            acc += f * __ldg(hw + w);
        }
        out[b] = acc;
    }
}

// ---------------- launch ----------------

extern "C" void kernel_launch(void* const* d_in, const int* in_sizes, int n_in,
                              void* d_out, int out_size)
{
    const float* sr = (const float*)d_in[0];
    const float* si = (const float*)d_in[1];
    const float* vp = (const float*)d_in[2];
    const float* hw = (const float*)d_in[3];
    const float* hb = (const float*)d_in[4];
    float* out = (float*)d_out;

    const int SMEM = DIM*sizeof(float2) + NTAB*sizeof(float4) + 3*NW*sizeof(float2);

    cudaFuncSetAttribute(qsim_kernel, cudaFuncAttributeMaxDynamicSharedMemorySize, SMEM);

    setup_all<<<1, 1024>>>(vp);

    int B = in_sizes[0] / DIM;
    qsim_kernel<<<B, NT, SMEM>>>(sr, si, hw, hb, out);
}